// round 5
// baseline (speedup 1.0000x reference)
#include <cuda_runtime.h>
#include <cuda_bf16.h>

#define SDIM 1024
#define BDIM 256
// fixed-point scale for deterministic integer atomic accumulation
#define FPSCALE 4294967296.0  // 2^32

// Grid-reduction scratch. Zero-initialized at module load; the last block to
// finish resets them to 0 after producing the output, so every graph replay
// sees clean state (deterministic: integer atomics are exact & commutative).
__device__ unsigned long long g_sum_acc = 0ULL;
__device__ unsigned long long g_cnt_acc = 0ULL;
__device__ unsigned int       g_done    = 0u;

__global__ void loss_kernel(const float* __restrict__ yp,
                            const int*   __restrict__ gt,
                            float*       __restrict__ out)
{
    const int b = blockIdx.x;   // one block per batch element
    const int t = threadIdx.x;  // 256 threads

    // ---- 1) block-redundant exact reduction of S0, S1, Q over all gt ----
    __shared__ long long r0[BDIM], r1[BDIM], rq[BDIM];
    const int g0 = gt[2 * t];
    const int g1 = gt[2 * t + 1];
    r0[t] = g0;
    r1[t] = g1;
    rq[t] = (long long)g0 * g0 + (long long)g1 * g1;
    __syncthreads();
#pragma unroll
    for (int s = 128; s > 0; s >>= 1) {
        if (t < s) { r0[t] += r0[t + s]; r1[t] += r1[t + s]; rq[t] += rq[t + s]; }
        __syncthreads();
    }
    const long long S0 = r0[0];
    const long long S1 = r1[0];
    const long long Q  = rq[0];

    // ---- 2) 36 window terms for this batch (threads 0..35) ----
    const int bg0 = gt[2 * b];
    const int bg1 = gt[2 * b + 1];

    double term = 0.0;
    int    vld  = 0;
    if (t < 36) {
        const int p0 = bg0 + t / 6 - 3;
        const int p1 = bg1 + t % 6 - 3;
        if (p0 >= 0 && p0 < SDIM && p1 >= 0 && p1 < SDIM) {
            vld = 1;
            const float y_hat = yp[(size_t)b * (SDIM * SDIM) + (size_t)p0 * SDIM + p1];
            // sq = sum_{b'} ||pos - gt[b']||^2, exact closed form
            const long long sq =
                (long long)BDIM * ((long long)p0 * p0 + (long long)p1 * p1)
                - 2LL * ((long long)p0 * S0 + (long long)p1 * S1) + Q;
            const float y = expf(-(float)sq * 0.2f);
            const float d = y_hat - y;
            float tm;
            if (y == 1.0f) {
                tm = -logf(y_hat) * d * d;
            } else {
                const float om  = 1.0f - y;
                const float om2 = om * om;
                tm = -logf(1.0f - y_hat) * om2 * om2 * d * d;
            }
            term = (double)tm;
        }
    }

    // ---- 3) block reduction of (term, valid) ----
    __shared__ double sterm[BDIM];
    __shared__ int    svld[BDIM];
    sterm[t] = term;
    svld[t]  = vld;
    __syncthreads();
#pragma unroll
    for (int s = 128; s > 0; s >>= 1) {
        if (t < s) { sterm[t] += sterm[t + s]; svld[t] += svld[t + s]; }
        __syncthreads();
    }

    // ---- 4) deterministic grid accumulation + last-block epilogue ----
    if (t == 0) {
        const unsigned long long q =
            (unsigned long long)(sterm[0] * FPSCALE + 0.5);
        atomicAdd(&g_sum_acc, q);
        atomicAdd(&g_cnt_acc, (unsigned long long)svld[0]);
        __threadfence();
        const unsigned int done = atomicAdd(&g_done, 1u);
        if (done == gridDim.x - 1) {
            // atomics (L2) to read the final values coherently
            const unsigned long long sum_q = atomicAdd(&g_sum_acc, 0ULL);
            const unsigned long long cnt   = atomicAdd(&g_cnt_acc, 0ULL);
            const double total = (double)sum_q / FPSCALE;
            out[0] = (float)(total / (double)cnt);
            // reset for the next graph replay
            g_sum_acc = 0ULL;
            g_cnt_acc = 0ULL;
            g_done    = 0u;
        }
    }
}

extern "C" void kernel_launch(void* const* d_in, const int* in_sizes, int n_in,
                              void* d_out, int out_size)
{
    const float* y_predict = (const float*)d_in[0];
    const int*   gt_pos    = (const int*)d_in[1];
    float*       out       = (float*)d_out;
    loss_kernel<<<BDIM, BDIM>>>(y_predict, gt_pos, out);
}